// round 11
// baseline (speedup 1.0000x reference)
#include <cuda_runtime.h>
#include <cstdint>

// Problem constants
#define N_NODES  8192
#define CH       128
#define NEXP     64
#define NODES_PER_CHUNK 16
#define MAX_PAD  9216
#define MAX_CHK  576

#define KT        32
#define ROW_BYTES 144                      // 32 words + 16B pad -> conflict-free ldmatrix
#define STAGE     (2 * 128 * ROW_BYTES)    // 36864: A tile + B tile
#define NSTAGES   4                        // ALL of K resident at once
#define SMEM_NODE (NSTAGES * STAGE)        // 147456
#define SMEM_TOTAL (SMEM_NODE + 64)

#define GEMM_THREADS 512

// Scratch
__device__ int   g_sorted[MAX_PAD];
__device__ int   g_chunk_expert[MAX_CHK];
__device__ float g_Wr[NEXP * CH * CH];     // tf32-rounded W

// ---------------------------------------------------------------------------
// helpers
// ---------------------------------------------------------------------------
__device__ __forceinline__ uint32_t smem_u32(const void* p) {
    uint32_t a;
    asm("{ .reg .u64 t; cvta.to.shared.u64 t, %1; cvt.u32.u64 %0, t; }"
        : "=r"(a) : "l"(p));
    return a;
}

__device__ __forceinline__ uint32_t f2tf32(float f) {
    uint32_t u;
    asm("cvt.rna.tf32.f32 %0, %1;" : "=r"(u) : "f"(f));
    return u;
}

__device__ __forceinline__ void cp16(uint32_t dst, const void* src, int sz) {
    asm volatile("cp.async.cg.shared.global [%0], [%1], 16, %2;"
                 :: "r"(dst), "l"(src), "r"(sz) : "memory");
}
__device__ __forceinline__ void cp_commit() {
    asm volatile("cp.async.commit_group;" ::: "memory");
}
template <int N>
__device__ __forceinline__ void cp_wait() {
    asm volatile("cp.async.wait_group %0;" :: "n"(N) : "memory");
}

__device__ __forceinline__ void ldsm_x4(uint32_t* r, uint32_t addr) {
    asm volatile("ldmatrix.sync.aligned.m8n8.x4.shared.b16 {%0,%1,%2,%3}, [%4];"
                 : "=r"(r[0]), "=r"(r[1]), "=r"(r[2]), "=r"(r[3])
                 : "r"(addr));
}

__device__ __forceinline__ void mma_tf32(float* d, const uint32_t* a, const uint32_t* b) {
    asm volatile(
        "mma.sync.aligned.m16n8k8.row.col.f32.tf32.tf32.f32 "
        "{%0,%1,%2,%3}, {%4,%5,%6,%7}, {%8,%9}, {%0,%1,%2,%3};\n"
        : "+f"(d[0]), "+f"(d[1]), "+f"(d[2]), "+f"(d[3])
        : "r"(a[0]), "r"(a[1]), "r"(a[2]), "r"(a[3]),
          "r"(b[0]), "r"(b[1]));
}

// ---------------------------------------------------------------------------
// K_prep (64 CTAs x 256): CTA e owns expert e. No cross-CTA dependencies.
// (R10-proven; unchanged)
// ---------------------------------------------------------------------------
__global__ __launch_bounds__(256, 2)
void prep_kernel(const float* __restrict__ W,
                 const long long* __restrict__ sel64) {
    const int tid = threadIdx.x;
    const int e   = blockIdx.x;

    __shared__ int bad;
    __shared__ int hist[NEXP];
    __shared__ int pads[NEXP];
    __shared__ int sc[NEXP];
    __shared__ int tc[256];

    // ---- W rounding slice: 4096 float4 per CTA ----
#pragma unroll
    for (int j = 0; j < 16; j++) {
        int i = e * 4096 + j * 256 + tid;
        float4 v = ((const float4*)W)[i];
        uint4 t;
        t.x = f2tf32(v.x); t.y = f2tf32(v.y);
        t.z = f2tf32(v.z); t.w = f2tf32(v.w);
        ((uint4*)g_Wr)[i] = t;
    }

    // ---- dtype detect: 64 int64 words (512B; safe for min buffer) ----
    if (tid == 0) bad = 0;
    if (tid < NEXP) hist[tid] = 0;
    __syncthreads();
    if (tid < 64) {
        long long v = sel64[tid];
        if (v < 0 || v >= NEXP) atomicOr(&bad, 1);
    }
    __syncthreads();
    const int is64 = bad ? 0 : 1;

    // ---- load my 32 contiguous sel values ----
    int v[32];
    if (is64) {
        const longlong2* p = (const longlong2*)sel64 + tid * 16;
#pragma unroll
        for (int i = 0; i < 16; i++) {
            longlong2 q = p[i];
            v[2 * i]     = (int)q.x;
            v[2 * i + 1] = (int)q.y;
        }
    } else {
        const int4* p = (const int4*)sel64 + tid * 8;
#pragma unroll
        for (int i = 0; i < 8; i++) {
            int4 q = p[i];
            v[4 * i] = q.x; v[4 * i + 1] = q.y;
            v[4 * i + 2] = q.z; v[4 * i + 3] = q.w;
        }
    }

    int myc = 0;
#pragma unroll
    for (int i = 0; i < 32; i++) {
        atomicAdd(&hist[v[i]], 1);
        myc += (v[i] == e);
    }
    __syncthreads();

    if (tid < NEXP) {
        int pd = (hist[tid] + NODES_PER_CHUNK - 1) & ~(NODES_PER_CHUNK - 1);
        pads[tid] = pd;
        sc[tid] = pd;
    }
    __syncthreads();
#pragma unroll
    for (int d = 1; d < NEXP; d <<= 1) {
        int t = 0;
        if (tid < NEXP && tid >= d) t = sc[tid - d];
        __syncthreads();
        if (tid < NEXP) sc[tid] += t;
        __syncthreads();
    }
    const int offs_e = sc[e] - pads[e];
    const int cnt_e  = hist[e];
    const int pad_e  = pads[e];
    const int total  = sc[NEXP - 1];

    tc[tid] = myc;
    __syncthreads();
#pragma unroll
    for (int d = 1; d < 256; d <<= 1) {
        int t = 0;
        if (tid >= d) t = tc[tid - d];
        __syncthreads();
        tc[tid] += t;
        __syncthreads();
    }
    int w = offs_e + tc[tid] - myc;

#pragma unroll
    for (int i = 0; i < 32; i++)
        if (v[i] == e) g_sorted[w++] = tid * 32 + i;

    for (int i = cnt_e + tid; i < pad_e; i += 256)
        g_sorted[offs_e + i] = -1;

    for (int c = offs_e / NODES_PER_CHUNK + tid;
         c < (offs_e + pad_e) / NODES_PER_CHUNK; c += 256)
        g_chunk_expert[c] = e;
    if (e == 0)
        for (int c = total / NODES_PER_CHUNK + tid; c < MAX_CHK; c += 256)
            g_chunk_expert[c] = -1;
}

// ---------------------------------------------------------------------------
// K_gemm: 512 threads, 1 CTA/SM. ALL 4 k-tiles resident in smem (147KB),
// all loads issued in prologue -> k-loop has no exposed memory waits after
// tile 0. 16 warps, 4x4 grid, warp tile 32x32. tf32 mma.sync + ldmatrix.
// ---------------------------------------------------------------------------
extern __shared__ char smem[];

__global__ __launch_bounds__(GEMM_THREADS, 1)
void grouped_gemm_kernel(const float* __restrict__ x,
                         float* __restrict__ out) {
    const int e = g_chunk_expert[blockIdx.x];
    if (e < 0) return;

    int* snode = (int*)(smem + SMEM_NODE);
    const int tid  = threadIdx.x;
    const int lane = tid & 31;
    const int warp = tid >> 5;
    const int warp_m = (warp & 3) * 32;
    const int warp_n = (warp >> 2) * 32;

    if (tid < NODES_PER_CHUNK)
        snode[tid] = g_sorted[blockIdx.x * NODES_PER_CHUNK + tid];
    __syncthreads();

    const uint32_t sbase = smem_u32(smem);

    // --- per-thread cp.async source/dest: 2 (A,B) chunk pairs per tile ---
    const float* xa[2];
    const float* wa[2];
    uint32_t da[2], db[2];
    int      asz[2];
    const float* Wre = g_Wr + (size_t)e * CH * CH;
#pragma unroll
    for (int i = 0; i < 2; i++) {
        int id  = tid + i * GEMM_THREADS;   // 0..1023
        int row = id >> 3;                  // 0..127
        int cq  = id & 7;
        int node = snode[row >> 3];
        asz[i] = (node >= 0) ? 16 : 0;
        if (node < 0) node = 0;
        xa[i] = x + ((size_t)(row & 7) * N_NODES + node) * CH + cq * 4;
        wa[i] = Wre + (size_t)row * CH + cq * 4;
        da[i] = sbase + (uint32_t)row * ROW_BYTES + cq * 16;
        db[i] = sbase + (uint32_t)(128 * ROW_BYTES) + (uint32_t)row * ROW_BYTES + cq * 16;
    }

    // --- ldmatrix base addresses (tile 0) ---
    uint32_t a_addr[2], b_addr[2];
    {
        int arow  = warp_m + (lane & 15);
        int abyte = (lane >> 4) * 16;
#pragma unroll
        for (int mt = 0; mt < 2; mt++)
            a_addr[mt] = sbase + (uint32_t)(arow + mt * 16) * ROW_BYTES + abyte;

        int brow  = warp_n + ((lane >> 4) << 3) + (lane & 7);
        int bbyte = ((lane >> 3) & 1) * 16;
#pragma unroll
        for (int p = 0; p < 2; p++)
            b_addr[p] = sbase + (uint32_t)(128 * ROW_BYTES)
                      + (uint32_t)(brow + p * 16) * ROW_BYTES + bbyte;
    }

    float acc[2][4][4];
#pragma unroll
    for (int mt = 0; mt < 2; mt++)
#pragma unroll
        for (int nt = 0; nt < 4; nt++)
#pragma unroll
            for (int i = 0; i < 4; i++) acc[mt][nt][i] = 0.0f;

    // --- prologue: issue ALL 4 k-tiles ---
#pragma unroll
    for (int t = 0; t < 4; t++) {
        uint32_t so = t * STAGE;
        int go = t * KT;
#pragma unroll
        for (int i = 0; i < 2; i++) {
            cp16(da[i] + so, xa[i] + go, asz[i]);
            cp16(db[i] + so, wa[i] + go, 16);
        }
        cp_commit();
    }

    // --- k-loop: waits are satisfied by in-flight data after tile 0 ---
#pragma unroll
    for (int k = 0; k < 4; k++) {
        if (k == 0)      cp_wait<3>();
        else if (k == 1) cp_wait<2>();
        else if (k == 2) cp_wait<1>();
        else             cp_wait<0>();
        __syncthreads();

        const uint32_t so = k * STAGE;
#pragma unroll
        for (int ks = 0; ks < 4; ks++) {
            uint32_t a[2][4], b[2][4];
#pragma unroll
            for (int mt = 0; mt < 2; mt++)
                ldsm_x4(a[mt], a_addr[mt] + so + ks * 32);
#pragma unroll
            for (int p = 0; p < 2; p++)
                ldsm_x4(b[p], b_addr[p] + so + ks * 32);
#pragma unroll
            for (int mt = 0; mt < 2; mt++)
#pragma unroll
                for (int nt = 0; nt < 4; nt++)
                    mma_tf32(acc[mt][nt], a[mt], &b[nt >> 1][(nt & 1) * 2]);
        }
    }

    // --- epilogue: direct scattered stores ---
    const int g = lane >> 2;
    const int c = lane & 3;
#pragma unroll
    for (int mt = 0; mt < 2; mt++) {
#pragma unroll
        for (int half = 0; half < 2; half++) {
            int r = warp_m + mt * 16 + g + half * 8;
            int node = snode[r >> 3];
            if (node < 0) continue;
            float* o = out + ((size_t)(r & 7) * N_NODES + node) * CH + warp_n;
#pragma unroll
            for (int nt = 0; nt < 4; nt++) {
                float2 v2 = make_float2(acc[mt][nt][half * 2],
                                        acc[mt][nt][half * 2 + 1]);
                *(float2*)(o + nt * 8 + c * 2) = v2;
            }
        }
    }
}

// ---------------------------------------------------------------------------
extern "C" void kernel_launch(void* const* d_in, const int* in_sizes, int n_in,
                              void* d_out, int out_size) {
    const float*     x   = (const float*)d_in[0];
    const long long* sel = (const long long*)d_in[1];
    const float*     W   = (const float*)d_in[2];
    float*           out = (float*)d_out;

    static bool attr_set = false;
    if (!attr_set) {
        cudaFuncSetAttribute(grouped_gemm_kernel,
                             cudaFuncAttributeMaxDynamicSharedMemorySize,
                             SMEM_TOTAL);
        attr_set = true;
    }

    prep_kernel<<<NEXP, 256>>>(W, sel);
    grouped_gemm_kernel<<<MAX_CHK, GEMM_THREADS, SMEM_TOTAL>>>(x, out);
}

// round 12
// speedup vs baseline: 1.1317x; 1.1317x over previous
#include <cuda_runtime.h>
#include <cstdint>

// Problem constants
#define N_NODES  8192
#define CH       128
#define NEXP     64
#define NODES_PER_CHUNK 32              // nodes per GEMM CTA (2 subtiles of 16)
#define SUBN     16
#define MAX_PAD  10240                  // 8192 + 64*32
#define MAX_CHK  320                    // MAX_PAD / 32

#define KT        32
#define ROW_BYTES 144                   // 32 words + 16B pad -> conflict-free ldmatrix
#define STAGE     (2 * 128 * ROW_BYTES) // 36864: A tile + B tile
#define NSTAGES   3
#define SMEM_NODE (NSTAGES * STAGE)     // 110592
#define SMEM_TOTAL (SMEM_NODE + 128)

// Scratch
__device__ int   g_sorted[MAX_PAD];
__device__ int   g_chunk_expert[MAX_CHK];
__device__ float g_Wr[NEXP * CH * CH];  // tf32-rounded W

// ---------------------------------------------------------------------------
// helpers
// ---------------------------------------------------------------------------
__device__ __forceinline__ uint32_t smem_u32(const void* p) {
    uint32_t a;
    asm("{ .reg .u64 t; cvta.to.shared.u64 t, %1; cvt.u32.u64 %0, t; }"
        : "=r"(a) : "l"(p));
    return a;
}

__device__ __forceinline__ uint32_t f2tf32(float f) {
    uint32_t u;
    asm("cvt.rna.tf32.f32 %0, %1;" : "=r"(u) : "f"(f));
    return u;
}

__device__ __forceinline__ void cp16(uint32_t dst, const void* src, int sz) {
    asm volatile("cp.async.cg.shared.global [%0], [%1], 16, %2;"
                 :: "r"(dst), "l"(src), "r"(sz) : "memory");
}
__device__ __forceinline__ void cp_commit() {
    asm volatile("cp.async.commit_group;" ::: "memory");
}
template <int N>
__device__ __forceinline__ void cp_wait() {
    asm volatile("cp.async.wait_group %0;" :: "n"(N) : "memory");
}

__device__ __forceinline__ void ldsm_x4(uint32_t* r, uint32_t addr) {
    asm volatile("ldmatrix.sync.aligned.m8n8.x4.shared.b16 {%0,%1,%2,%3}, [%4];"
                 : "=r"(r[0]), "=r"(r[1]), "=r"(r[2]), "=r"(r[3])
                 : "r"(addr));
}

__device__ __forceinline__ void mma_tf32(float* d, const uint32_t* a, const uint32_t* b) {
    asm volatile(
        "mma.sync.aligned.m16n8k8.row.col.f32.tf32.tf32.f32 "
        "{%0,%1,%2,%3}, {%4,%5,%6,%7}, {%8,%9}, {%0,%1,%2,%3};\n"
        : "+f"(d[0]), "+f"(d[1]), "+f"(d[2]), "+f"(d[3])
        : "r"(a[0]), "r"(a[1]), "r"(a[2]), "r"(a[3]),
          "r"(b[0]), "r"(b[1]));
}

// ---------------------------------------------------------------------------
// K_prep (64 CTAs x 256): CTA e owns expert e. No cross-CTA dependencies.
// Pads expert regions to 32 nodes (GEMM chunk size).
// ---------------------------------------------------------------------------
__global__ __launch_bounds__(256, 2)
void prep_kernel(const float* __restrict__ W,
                 const long long* __restrict__ sel64) {
    const int tid = threadIdx.x;
    const int e   = blockIdx.x;

    __shared__ int bad;
    __shared__ int hist[NEXP];
    __shared__ int pads[NEXP];
    __shared__ int sc[NEXP];
    __shared__ int tc[256];

    // ---- W rounding slice: 4096 float4 per CTA ----
#pragma unroll
    for (int j = 0; j < 16; j++) {
        int i = e * 4096 + j * 256 + tid;
        float4 v = ((const float4*)W)[i];
        uint4 t;
        t.x = f2tf32(v.x); t.y = f2tf32(v.y);
        t.z = f2tf32(v.z); t.w = f2tf32(v.w);
        ((uint4*)g_Wr)[i] = t;
    }

    // ---- dtype detect: 64 int64 words (512B; safe for min buffer) ----
    if (tid == 0) bad = 0;
    if (tid < NEXP) hist[tid] = 0;
    __syncthreads();
    if (tid < 64) {
        long long v = sel64[tid];
        if (v < 0 || v >= NEXP) atomicOr(&bad, 1);
    }
    __syncthreads();
    const int is64 = bad ? 0 : 1;

    // ---- load my 32 contiguous sel values ----
    int v[32];
    if (is64) {
        const longlong2* p = (const longlong2*)sel64 + tid * 16;
#pragma unroll
        for (int i = 0; i < 16; i++) {
            longlong2 q = p[i];
            v[2 * i]     = (int)q.x;
            v[2 * i + 1] = (int)q.y;
        }
    } else {
        const int4* p = (const int4*)sel64 + tid * 8;
#pragma unroll
        for (int i = 0; i < 8; i++) {
            int4 q = p[i];
            v[4 * i] = q.x; v[4 * i + 1] = q.y;
            v[4 * i + 2] = q.z; v[4 * i + 3] = q.w;
        }
    }

    int myc = 0;
#pragma unroll
    for (int i = 0; i < 32; i++) {
        atomicAdd(&hist[v[i]], 1);
        myc += (v[i] == e);
    }
    __syncthreads();

    if (tid < NEXP) {
        int pd = (hist[tid] + NODES_PER_CHUNK - 1) & ~(NODES_PER_CHUNK - 1);
        pads[tid] = pd;
        sc[tid] = pd;
    }
    __syncthreads();
#pragma unroll
    for (int d = 1; d < NEXP; d <<= 1) {
        int t = 0;
        if (tid < NEXP && tid >= d) t = sc[tid - d];
        __syncthreads();
        if (tid < NEXP) sc[tid] += t;
        __syncthreads();
    }
    const int offs_e = sc[e] - pads[e];
    const int cnt_e  = hist[e];
    const int pad_e  = pads[e];
    const int total  = sc[NEXP - 1];

    tc[tid] = myc;
    __syncthreads();
#pragma unroll
    for (int d = 1; d < 256; d <<= 1) {
        int t = 0;
        if (tid >= d) t = tc[tid - d];
        __syncthreads();
        tc[tid] += t;
        __syncthreads();
    }
    int w = offs_e + tc[tid] - myc;

#pragma unroll
    for (int i = 0; i < 32; i++)
        if (v[i] == e) g_sorted[w++] = tid * 32 + i;

    for (int i = cnt_e + tid; i < pad_e; i += 256)
        g_sorted[offs_e + i] = -1;

    for (int c = offs_e / NODES_PER_CHUNK + tid;
         c < (offs_e + pad_e) / NODES_PER_CHUNK; c += 256)
        g_chunk_expert[c] = e;
    if (e == 0)
        for (int c = total / NODES_PER_CHUNK + tid; c < MAX_CHK; c += 256)
            g_chunk_expert[c] = -1;
}

// ---------------------------------------------------------------------------
// K_gemm: 256 threads, 2 CTAs/SM (R9-proven skeleton). Each CTA processes
// 32 nodes = 2 M-subtiles of 128 rows, streaming 8 tiles (sub0 k0..3,
// sub1 k0..3) through the same 3-stage cp.async pipeline. Sub1's B-tiles
// refetch from L2. Epilogue of sub0 overlaps sub1's loads.
// ---------------------------------------------------------------------------
extern __shared__ char smem[];

__global__ __launch_bounds__(256, 2)
void grouped_gemm_kernel(const float* __restrict__ x,
                         float* __restrict__ out) {
    const int e = g_chunk_expert[blockIdx.x];
    if (e < 0) return;

    int* snode = (int*)(smem + SMEM_NODE);
    const int tid  = threadIdx.x;
    const int lane = tid & 31;
    const int warp = tid >> 5;
    const int warp_m = (warp & 3) * 32;
    const int warp_n = (warp >> 2) * 64;

    if (tid < NODES_PER_CHUNK)
        snode[tid] = g_sorted[blockIdx.x * NODES_PER_CHUNK + tid];
    __syncthreads();

    const uint32_t sbase = smem_u32(smem);
    const float* Wre = g_Wr + (size_t)e * CH * CH;

    // --- per-thread load geometry (4 chunks each for A and B per tile) ---
    // chunk id = tid + i*256: row = id>>3 (0..127), cq = id&7
    const float* pA[4];   // x + (row&7)*N_NODES*CH + cq*4   (add node*CH + k*KT)
    const float* pB[4];   // Wre + row*CH + cq*4             (add k*KT)
    uint32_t da[4], db[4];
    int      rs[4];       // row>>3 : node slot within subtile
#pragma unroll
    for (int i = 0; i < 4; i++) {
        int id  = tid + i * 256;
        int row = id >> 3;
        int cq  = id & 7;
        rs[i] = row >> 3;
        pA[i] = x + (size_t)(row & 7) * N_NODES * CH + cq * 4;
        pB[i] = Wre + (size_t)row * CH + cq * 4;
        da[i] = sbase + (uint32_t)row * ROW_BYTES + cq * 16;
        db[i] = sbase + (uint32_t)(128 * ROW_BYTES) + (uint32_t)row * ROW_BYTES + cq * 16;
    }

    // --- ldmatrix base addresses (stage 0) ---
    uint32_t a_addr[2], b_addr[4];
    {
        int arow  = warp_m + (lane & 15);
        int abyte = (lane >> 4) * 16;
#pragma unroll
        for (int mt = 0; mt < 2; mt++)
            a_addr[mt] = sbase + (uint32_t)(arow + mt * 16) * ROW_BYTES + abyte;

        int brow  = warp_n + ((lane >> 4) << 3) + (lane & 7);
        int bbyte = ((lane >> 3) & 1) * 16;
#pragma unroll
        for (int p = 0; p < 4; p++)
            b_addr[p] = sbase + (uint32_t)(128 * ROW_BYTES)
                      + (uint32_t)(brow + p * 16) * ROW_BYTES + bbyte;
    }

    // tile t (0..7): sub = t>>2, k = t&3, stage = t%3
    auto issue_tile = [&](int t) {
        const int sub = t >> 2;
        const int k   = t & 3;
        const uint32_t so = (uint32_t)(t % NSTAGES) * STAGE;
#pragma unroll
        for (int i = 0; i < 4; i++) {
            int node = snode[sub * SUBN + rs[i]];
            int sz = (node >= 0) ? 16 : 0;
            int nn = (node < 0) ? 0 : node;
            cp16(da[i] + so, pA[i] + (size_t)nn * CH + k * KT, sz);
            cp16(db[i] + so, pB[i] + k * KT, 16);
        }
        cp_commit();
    };

    float acc[2][8][4];
#pragma unroll
    for (int mt = 0; mt < 2; mt++)
#pragma unroll
        for (int nt = 0; nt < 8; nt++)
#pragma unroll
            for (int i = 0; i < 4; i++) acc[mt][nt][i] = 0.0f;

    const int g = lane >> 2;
    const int c = lane & 3;
    auto epilogue = [&](int sub) {
#pragma unroll
        for (int mt = 0; mt < 2; mt++) {
#pragma unroll
            for (int half = 0; half < 2; half++) {
                int r = warp_m + mt * 16 + g + half * 8;
                int node = snode[sub * SUBN + (r >> 3)];
                if (node < 0) continue;
                float* o = out + ((size_t)(r & 7) * N_NODES + node) * CH + warp_n;
#pragma unroll
                for (int nt = 0; nt < 8; nt++) {
                    float2 v2 = make_float2(acc[mt][nt][half * 2],
                                            acc[mt][nt][half * 2 + 1]);
                    *(float2*)(o + nt * 8 + c * 2) = v2;
                }
            }
        }
    };

    // prologue: tiles 0 and 1
    issue_tile(0);
    issue_tile(1);

#pragma unroll
    for (int j = 0; j < 8; j++) {
        if (j < 7) cp_wait<1>();
        else       cp_wait<0>();
        __syncthreads();

        if (j + 2 < 8) issue_tile(j + 2);

        const uint32_t so = (uint32_t)(j % NSTAGES) * STAGE;
#pragma unroll
        for (int ks = 0; ks < 4; ks++) {
            uint32_t a[2][4], b[4][4];
#pragma unroll
            for (int mt = 0; mt < 2; mt++)
                ldsm_x4(a[mt], a_addr[mt] + so + ks * 32);
#pragma unroll
            for (int p = 0; p < 4; p++)
                ldsm_x4(b[p], b_addr[p] + so + ks * 32);
#pragma unroll
            for (int mt = 0; mt < 2; mt++)
#pragma unroll
                for (int nt = 0; nt < 8; nt++)
                    mma_tf32(acc[mt][nt], a[mt], &b[nt >> 1][(nt & 1) * 2]);
        }

        if (j == 3) {
            epilogue(0);       // overlaps tiles 4,5 in flight
#pragma unroll
            for (int mt = 0; mt < 2; mt++)
#pragma unroll
                for (int nt = 0; nt < 8; nt++)
#pragma unroll
                    for (int i = 0; i < 4; i++) acc[mt][nt][i] = 0.0f;
        }
    }

    epilogue(1);
}

// ---------------------------------------------------------------------------
extern "C" void kernel_launch(void* const* d_in, const int* in_sizes, int n_in,
                              void* d_out, int out_size) {
    const float*     x   = (const float*)d_in[0];
    const long long* sel = (const long long*)d_in[1];
    const float*     W   = (const float*)d_in[2];
    float*           out = (float*)d_out;

    static bool attr_set = false;
    if (!attr_set) {
        cudaFuncSetAttribute(grouped_gemm_kernel,
                             cudaFuncAttributeMaxDynamicSharedMemorySize,
                             SMEM_TOTAL);
        attr_set = true;
    }

    prep_kernel<<<NEXP, 256>>>(W, sel);
    grouped_gemm_kernel<<<MAX_CHK, 256, SMEM_TOTAL>>>(x, out);
}